// round 9
// baseline (speedup 1.0000x reference)
#include <cuda_runtime.h>
#include <cuda_bf16.h>
#include <cstdint>

#define NN 100000
#define NE 800000
#define DD 256

// ---------------- device scratch (no allocations allowed) ----------------
__device__ __align__(16) float g_bufA[(size_t)NN * DD];            // GEMM out (dis-scaled h)
__device__ __align__(16) __nv_bfloat16 g_Ah[(size_t)NN * DD];      // A operand hi (x-split / relu out)
__device__ __align__(16) __nv_bfloat16 g_Al[(size_t)NN * DD];      // A operand lo
__device__ int   g_indeg[NN];
__device__ int   g_off[NN];
__device__ int   g_cursor[NN];
__device__ int   g_csrc[NE];
__device__ int   g_total;
// W split hi/lo, pre-transposed to [N][K] bf16 (B operand, K-contiguous)
__device__ __align__(16) __nv_bfloat16 g_W1h[256 * 256], g_W1l[256 * 256];
__device__ __align__(16) __nv_bfloat16 g_W2h[256 * 256], g_W2l[256 * 256];
__device__ __align__(16) __nv_bfloat16 g_Woh[64 * 256],  g_Wol[64 * 256];

// ---------------- PTX helpers (valid on compute_103) ----------------
__device__ __forceinline__ uint32_t smem_u32(const void* p) {
    uint32_t a;
    asm("{ .reg .u64 t; cvta.to.shared.u64 t, %1; cvt.u32.u64 %0, t; }" : "=r"(a) : "l"(p));
    return a;
}
__device__ __forceinline__ void ldsm4(uint32_t r[4], uint32_t addr) {
    asm volatile("ldmatrix.sync.aligned.m8n8.x4.shared.b16 {%0,%1,%2,%3}, [%4];"
                 : "=r"(r[0]), "=r"(r[1]), "=r"(r[2]), "=r"(r[3]) : "r"(addr));
}
__device__ __forceinline__ void mma16816(float c[4], const uint32_t a[4],
                                         uint32_t b0, uint32_t b1) {
    asm volatile(
        "mma.sync.aligned.m16n8k16.row.col.f32.bf16.bf16.f32 "
        "{%0,%1,%2,%3}, {%4,%5,%6,%7}, {%8,%9}, {%0,%1,%2,%3};"
        : "+f"(c[0]), "+f"(c[1]), "+f"(c[2]), "+f"(c[3])
        : "r"(a[0]), "r"(a[1]), "r"(a[2]), "r"(a[3]), "r"(b0), "r"(b1));
}
__device__ __forceinline__ void cpa16(uint32_t dst, const void* src, int sz) {
    asm volatile("cp.async.cg.shared.global [%0], [%1], 16, %2;"
                 :: "r"(dst), "l"(src), "r"(sz) : "memory");
}
#define CP_COMMIT() asm volatile("cp.async.commit_group;" ::: "memory")
#define CP_WAIT(n)  asm volatile("cp.async.wait_group %0;" :: "n"(n) : "memory")

// split two fp32 -> packed bf16 hi pair + lo pair
__device__ __forceinline__ void split2(float f0, float f1, uint32_t& h, uint32_t& l) {
    __nv_bfloat16 h0 = __float2bfloat16(f0), h1 = __float2bfloat16(f1);
    __nv_bfloat16 l0 = __float2bfloat16(f0 - __bfloat162float(h0));
    __nv_bfloat16 l1 = __float2bfloat16(f1 - __bfloat162float(h1));
    h = (uint32_t)*(uint16_t*)&h0 | ((uint32_t)*(uint16_t*)&h1 << 16);
    l = (uint32_t)*(uint16_t*)&l0 | ((uint32_t)*(uint16_t*)&l1 << 16);
}

// ---------------- x -> bf16 hi/lo split ----------------
__global__ void k_splitX(const float* __restrict__ x) {
    size_t i = (size_t)(blockIdx.x * 256 + threadIdx.x) * 4;
    float4 v = *(const float4*)(x + i);
    uint32_t h0, l0, h1, l1;
    split2(v.x, v.y, h0, l0);
    split2(v.z, v.w, h1, l1);
    *(uint2*)(g_Ah + i) = make_uint2(h0, h1);
    *(uint2*)(g_Al + i) = make_uint2(l0, l1);
}

// ---------------- init: zero degrees + split/transpose weights ----------------
__global__ void k_init(const float* __restrict__ W1, const float* __restrict__ W2,
                       const float* __restrict__ Wo) {
    int i = blockIdx.x * 256 + threadIdx.x;
    if (i < NN) g_indeg[i] = 0;
    if (i == 0) g_total = 0;
    if (i < 65536) {
        int n = i >> 8, k = i & 255;
        float a = W1[(size_t)k * 256 + n];
        __nv_bfloat16 h = __float2bfloat16(a);
        g_W1h[i] = h;
        g_W1l[i] = __float2bfloat16(a - __bfloat162float(h));
        a = W2[(size_t)k * 256 + n];
        h = __float2bfloat16(a);
        g_W2h[i] = h;
        g_W2l[i] = __float2bfloat16(a - __bfloat162float(h));
        if (i < 16384) {
            int n2 = i >> 8, k2 = i & 255;
            a = Wo[(size_t)k2 * 64 + n2];
            h = __float2bfloat16(a);
            g_Woh[i] = h;
            g_Wol[i] = __float2bfloat16(a - __bfloat162float(h));
        }
    }
}
__global__ void k_deg(const int* __restrict__ dst) {
    int e = blockIdx.x * 256 + threadIdx.x;
    if (e < NE) atomicAdd(&g_indeg[dst[e]], 1);
}
// parallel offset assignment: warp scan + one atomic per warp (order-free CSR)
__global__ void k_off() {
    int i = blockIdx.x * 256 + threadIdx.x;
    int lane = threadIdx.x & 31;
    int d = (i < NN) ? g_indeg[i] : 0;
    int v = d;
    #pragma unroll
    for (int s = 1; s < 32; s <<= 1) {
        int t = __shfl_up_sync(0xffffffffu, v, s);
        if (lane >= s) v += t;
    }
    int wtotal = __shfl_sync(0xffffffffu, v, 31);
    int base = 0;
    if (lane == 0) base = atomicAdd(&g_total, wtotal);
    base = __shfl_sync(0xffffffffu, base, 0);
    if (i < NN) {
        int excl = base + v - d;
        g_off[i] = excl;
        g_cursor[i] = excl;
    }
}
__global__ void k_fill(const int* __restrict__ src, const int* __restrict__ dst) {
    int e = blockIdx.x * 256 + threadIdx.x;
    if (e < NE) {
        int p = atomicAdd(&g_cursor[dst[e]], 1);
        g_csrc[p] = src[e];
    }
}

// ---------------- HMMA GEMM via cp.async: C = A[M,256] @ W, 3-pass bf16 split ----
// BM=128, BK=32, 256 thr (8 warps 4m x 2n), warp tile 32 x (BN/2). 2 CTAs/SM.
// Pass-major MMA issue: 8 independent MMAs between accumulator reuse.
// MODE 0/1: C=g_bufA, row-scale by rsqrt(indeg+1)
// MODE 2:   C=Cext, + bias + fused log_softmax (BN=64)
template <int MODE, int BN>
__global__ __launch_bounds__(256, 2)
void gemm_mma(const float* __restrict__ bias, float* __restrict__ Cext)
{
    float* C = (MODE == 2) ? Cext : (float*)g_bufA;
    const __nv_bfloat16* WH = (MODE == 0) ? g_W1h : (MODE == 1) ? g_W2h : g_Woh;
    const __nv_bfloat16* WL = (MODE == 0) ? g_W1l : (MODE == 1) ? g_W2l : g_Wol;

    constexpr int WN = BN / 2;               // 64 or 32
    constexpr int NT = WN / 8;               // 8 or 4
    constexpr int A_BYTES = 128 * 80;        // 10240 (LDSE=40 elems, 80B rows)
    constexpr int B_BYTES = BN * 80;
    constexpr int STAGE = 2 * A_BYTES + 2 * B_BYTES;
    constexpr int BH = BN / 64;              // B cp.async iterations (2 or 1)
    constexpr int CS = (MODE == 2) ? 64 : 256;

    extern __shared__ char smraw[];
    uint32_t sb = smem_u32(smraw);

    int tid = threadIdx.x, lane = tid & 31, wid = tid >> 5;
    int mw = wid & 3, nw = wid >> 2;
    int bm0 = blockIdx.x * 128;
    int bn0 = blockIdx.y * BN;

    auto issue = [&](int kb, int s) {
        uint32_t base = sb + (uint32_t)s * STAGE;
        #pragma unroll
        for (int h = 0; h < 2; h++) {
            int c = tid + h * 256;
            int row = c >> 2, kq = c & 3;
            int r = bm0 + row;
            uint32_t dst = base + (uint32_t)row * 80u + (uint32_t)kq * 16u;
            size_t gp = (size_t)r * DD + kb * 32 + kq * 8;
            int sz = (r < NN) ? 16 : 0;
            cpa16(dst, g_Ah + gp, sz);
            cpa16(dst + A_BYTES, g_Al + gp, sz);
        }
        #pragma unroll
        for (int h = 0; h < BH; h++) {
            int c = tid + h * 256;
            int row = c >> 2, kq = c & 3;
            uint32_t dst = base + 2 * A_BYTES + (uint32_t)row * 80u + (uint32_t)kq * 16u;
            size_t gp = (size_t)(bn0 + row) * DD + kb * 32 + kq * 8;
            cpa16(dst, WH + gp, 16);
            cpa16(dst + B_BYTES, WL + gp, 16);
        }
        CP_COMMIT();
    };

    float acc[2][NT][4];
    #pragma unroll
    for (int mt = 0; mt < 2; mt++)
        #pragma unroll
        for (int nt = 0; nt < NT; nt++)
            #pragma unroll
            for (int q = 0; q < 4; q++) acc[mt][nt][q] = 0.f;

    issue(0, 0);
    issue(1, 1);

    for (int kb = 0; kb < 8; kb++) {
        int s = kb & 1;
        if (kb < 7) { CP_WAIT(1); } else { CP_WAIT(0); }
        __syncthreads();

        // compute stage s — pass-major issue for MMA ILP
        {
            uint32_t base = sb + (uint32_t)s * STAGE;
            #pragma unroll
            for (int ks = 0; ks < 2; ks++) {
                int col = ks * 16 + (lane >> 4) * 8;
                uint32_t ah[2][4], al[2][4];
                uint32_t aoff = (uint32_t)((mw * 32 + (lane & 15)) * 40 + col) * 2u;
                ldsm4(ah[0], base + aoff);
                ldsm4(ah[1], base + aoff + 16 * 80);
                ldsm4(al[0], base + A_BYTES + aoff);
                ldsm4(al[1], base + A_BYTES + aoff + 16 * 80);

                #pragma unroll
                for (int g = 0; g < NT / 4; g++) {
                    // load B frags for 4 n-tiles (2 ldsm pairs)
                    uint32_t bh[4][2], bl[4][2];
                    #pragma unroll
                    for (int j2 = 0; j2 < 2; j2++) {
                        int j = g * 2 + j2;
                        uint32_t boff = base + 2 * A_BYTES +
                            (uint32_t)((nw * WN + j * 16 + (lane & 15)) * 40 + col) * 2u;
                        uint32_t rh[4], rl[4];
                        ldsm4(rh, boff);
                        ldsm4(rl, boff + B_BYTES);
                        bh[2 * j2][0] = rh[0]; bh[2 * j2][1] = rh[2];
                        bh[2 * j2 + 1][0] = rh[1]; bh[2 * j2 + 1][1] = rh[3];
                        bl[2 * j2][0] = rl[0]; bl[2 * j2][1] = rl[2];
                        bl[2 * j2 + 1][0] = rl[1]; bl[2 * j2 + 1][1] = rl[3];
                    }
                    // pass 1: hi*hi  (8 independent MMAs)
                    #pragma unroll
                    for (int mt = 0; mt < 2; mt++)
                        #pragma unroll
                        for (int q = 0; q < 4; q++)
                            mma16816(acc[mt][g * 4 + q], ah[mt], bh[q][0], bh[q][1]);
                    // pass 2: hi*lo
                    #pragma unroll
                    for (int mt = 0; mt < 2; mt++)
                        #pragma unroll
                        for (int q = 0; q < 4; q++)
                            mma16816(acc[mt][g * 4 + q], ah[mt], bl[q][0], bl[q][1]);
                    // pass 3: lo*hi
                    #pragma unroll
                    for (int mt = 0; mt < 2; mt++)
                        #pragma unroll
                        for (int q = 0; q < 4; q++)
                            mma16816(acc[mt][g * 4 + q], al[mt], bh[q][0], bh[q][1]);
                }
            }
        }
        if (kb < 6) {
            __syncthreads();
            issue(kb + 2, s);
        }
    }

    if (MODE != 2) {
        // ---- epilogue: inline dis = rsqrt(indeg+1), scale + store ----
        int rbase = bm0 + mw * 32 + (lane >> 2);
        int cbase = bn0 + nw * WN + (lane & 3) * 2;
        #pragma unroll
        for (int mt = 0; mt < 2; mt++) {
            int r0 = rbase + mt * 16, r1 = r0 + 8;
            float s0 = (r0 < NN) ? rsqrtf((float)(g_indeg[r0] + 1)) : 0.f;
            float s1 = (r1 < NN) ? rsqrtf((float)(g_indeg[r1] + 1)) : 0.f;
            #pragma unroll
            for (int nt = 0; nt < NT; nt++) {
                int cc = cbase + nt * 8;
                if (r0 < NN) *(float2*)(C + (size_t)r0 * CS + cc) =
                    make_float2(acc[mt][nt][0] * s0, acc[mt][nt][1] * s0);
                if (r1 < NN) *(float2*)(C + (size_t)r1 * CS + cc) =
                    make_float2(acc[mt][nt][2] * s1, acc[mt][nt][3] * s1);
            }
        }
    } else {
        // ---- epilogue: bias -> smem -> fused log_softmax -> store ----
        __syncthreads();   // all compute done before smem reuse
        float* ls = (float*)smraw;   // 128 x 64 fp32 = 32KB
        int lr0 = mw * 32 + (lane >> 2);
        int cb = nw * WN + (lane & 3) * 2;
        #pragma unroll
        for (int mt = 0; mt < 2; mt++) {
            int a0 = lr0 + mt * 16, a1 = a0 + 8;
            #pragma unroll
            for (int nt = 0; nt < NT; nt++) {
                int cc = cb + nt * 8;
                float b0 = bias[cc], b1 = bias[cc + 1];
                ls[a0 * 64 + cc] = acc[mt][nt][0] + b0;
                ls[a0 * 64 + cc + 1] = acc[mt][nt][1] + b1;
                ls[a1 * 64 + cc] = acc[mt][nt][2] + b0;
                ls[a1 * 64 + cc + 1] = acc[mt][nt][3] + b1;
            }
        }
        __syncthreads();
        #pragma unroll 1
        for (int i = 0; i < 16; i++) {
            int lr = wid * 16 + i;
            int r = bm0 + lr;
            if (r >= NN) break;
            float2 v = *(const float2*)&ls[lr * 64 + lane * 2];
            float m = fmaxf(v.x, v.y);
            #pragma unroll
            for (int d = 16; d; d >>= 1) m = fmaxf(m, __shfl_xor_sync(0xffffffffu, m, d));
            float sm = expf(v.x - m) + expf(v.y - m);
            #pragma unroll
            for (int d = 16; d; d >>= 1) sm += __shfl_xor_sync(0xffffffffu, sm, d);
            float l = m + logf(sm);
            *(float2*)(C + (size_t)r * 64 + lane * 2) = make_float2(v.x - l, v.y - l);
        }
    }
}

// ---------------- aggregation: relu(dis*(Hs[i]+sum Hs[src])+b) -> bf16 hi/lo split ----
__global__ __launch_bounds__(256)
void k_agg(const float* __restrict__ bias)
{
    int node = blockIdx.x * 8 + (threadIdx.x >> 5);
    int lane = threadIdx.x & 31;
    const float4* __restrict__ Hs = (const float4*)g_bufA;

    size_t base = (size_t)node * 64;
    float4 a0 = Hs[base + lane];
    float4 a1 = Hs[base + 32 + lane];

    int e = g_off[node], deg = g_indeg[node], end = e + deg;
    for (; e + 3 < end; e += 4) {
        int s0 = g_csrc[e], s1 = g_csrc[e + 1], s2 = g_csrc[e + 2], s3 = g_csrc[e + 3];
        size_t p0 = (size_t)s0 * 64, p1 = (size_t)s1 * 64;
        size_t p2 = (size_t)s2 * 64, p3 = (size_t)s3 * 64;
        float4 v0 = Hs[p0 + lane],      w0 = Hs[p1 + lane];
        float4 x0 = Hs[p2 + lane],      y0 = Hs[p3 + lane];
        float4 v1 = Hs[p0 + 32 + lane], w1 = Hs[p1 + 32 + lane];
        float4 x1 = Hs[p2 + 32 + lane], y1 = Hs[p3 + 32 + lane];
        a0.x += (v0.x + w0.x) + (x0.x + y0.x);
        a0.y += (v0.y + w0.y) + (x0.y + y0.y);
        a0.z += (v0.z + w0.z) + (x0.z + y0.z);
        a0.w += (v0.w + w0.w) + (x0.w + y0.w);
        a1.x += (v1.x + w1.x) + (x1.x + y1.x);
        a1.y += (v1.y + w1.y) + (x1.y + y1.y);
        a1.z += (v1.z + w1.z) + (x1.z + y1.z);
        a1.w += (v1.w + w1.w) + (x1.w + y1.w);
    }
    for (; e < end; e++) {
        int s0 = g_csrc[e];
        size_t p0 = (size_t)s0 * 64;
        float4 v0 = Hs[p0 + lane];
        float4 v1 = Hs[p0 + 32 + lane];
        a0.x += v0.x; a0.y += v0.y; a0.z += v0.z; a0.w += v0.w;
        a1.x += v1.x; a1.y += v1.y; a1.z += v1.z; a1.w += v1.w;
    }

    float dsc = rsqrtf((float)(deg + 1));
    float4 b0 = *(const float4*)(bias + lane * 4);
    float4 b1 = *(const float4*)(bias + 128 + lane * 4);
    float o00 = fmaxf(fmaf(dsc, a0.x, b0.x), 0.f);
    float o01 = fmaxf(fmaf(dsc, a0.y, b0.y), 0.f);
    float o02 = fmaxf(fmaf(dsc, a0.z, b0.z), 0.f);
    float o03 = fmaxf(fmaf(dsc, a0.w, b0.w), 0.f);
    float o10 = fmaxf(fmaf(dsc, a1.x, b1.x), 0.f);
    float o11 = fmaxf(fmaf(dsc, a1.y, b1.y), 0.f);
    float o12 = fmaxf(fmaf(dsc, a1.z, b1.z), 0.f);
    float o13 = fmaxf(fmaf(dsc, a1.w, b1.w), 0.f);

    size_t ob = (size_t)node * 256 + lane * 4;
    uint32_t h0, l0, h1, l1;
    split2(o00, o01, h0, l0);
    split2(o02, o03, h1, l1);
    *(uint2*)(g_Ah + ob) = make_uint2(h0, h1);
    *(uint2*)(g_Al + ob) = make_uint2(l0, l1);
    split2(o10, o11, h0, l0);
    split2(o12, o13, h1, l1);
    *(uint2*)(g_Ah + ob + 128) = make_uint2(h0, h1);
    *(uint2*)(g_Al + ob + 128) = make_uint2(l0, l1);
}

// ---------------- launch ----------------
extern "C" void kernel_launch(void* const* d_in, const int* in_sizes, int n_in,
                              void* d_out, int out_size)
{
    const float* x  = (const float*)d_in[0];
    const int*   ei = (const int*)d_in[1];
    const float* b1 = (const float*)d_in[3];
    const float* b2 = (const float*)d_in[5];
    const float* W1 = (const float*)d_in[2];
    const float* W2 = (const float*)d_in[4];
    const float* Wo = (const float*)d_in[6];
    const float* bo = (const float*)d_in[7];
    float* out = (float*)d_out;

    const int* src = ei;
    const int* dst = ei + NE;

    cudaFuncSetAttribute(gemm_mma<0, 128>, cudaFuncAttributeMaxDynamicSharedMemorySize, 81920);
    cudaFuncSetAttribute(gemm_mma<1, 128>, cudaFuncAttributeMaxDynamicSharedMemorySize, 81920);
    cudaFuncSetAttribute(gemm_mma<2, 64>,  cudaFuncAttributeMaxDynamicSharedMemorySize, 61440);

    const int GM = (NN + 127) / 128;   // 782

    k_splitX<<<NN * DD / 1024, 256>>>(x);                        // 1: x -> bf16 hi/lo
    k_init<<<(NN + 255) / 256, 256>>>(W1, W2, Wo);               // 2: zero deg + W split
    k_deg<<<NE / 256, 256>>>(dst);                               // 3: degrees
    gemm_mma<0, 128><<<dim3(GM, 2), 256, 81920>>>(nullptr, nullptr);  // 4: bufA = dis*(x@W1)
    k_off<<<(NN + 255) / 256, 256>>>();                          // 5: CSR offsets
    k_fill<<<NE / 256, 256>>>(src, dst);                         // 6: CSR fill
    k_agg<<<NN / 8, 256>>>(b1);                                  // 7: Ah/Al = split(relu(...))
    gemm_mma<1, 128><<<dim3(GM, 2), 256, 81920>>>(nullptr, nullptr);
    k_agg<<<NN / 8, 256>>>(b2);
    gemm_mma<2, 64><<<dim3(GM, 1), 256, 61440>>>(bo, out);       // out = lsm(h@Wo + bo)
}

// round 10
// speedup vs baseline: 1.2531x; 1.2531x over previous
#include <cuda_runtime.h>
#include <cuda_bf16.h>
#include <cstdint>

#define NN 100000
#define NE 800000
#define DD 256

// ---------------- device scratch (no allocations allowed) ----------------
__device__ __align__(16) float g_bufA[(size_t)NN * DD];            // GEMM out (dis-scaled h)
__device__ __align__(16) __nv_bfloat16 g_Ah[(size_t)NN * DD];      // A operand bf16 (x / relu out)
__device__ int   g_indeg[NN];
__device__ int   g_off[NN];
__device__ int   g_cursor[NN];
__device__ int   g_csrc[NE];
__device__ int   g_total;
// W split hi/lo, pre-transposed to [N][K] bf16 (B operand, K-contiguous)
__device__ __align__(16) __nv_bfloat16 g_W1h[256 * 256], g_W1l[256 * 256];
__device__ __align__(16) __nv_bfloat16 g_W2h[256 * 256], g_W2l[256 * 256];
__device__ __align__(16) __nv_bfloat16 g_Woh[64 * 256],  g_Wol[64 * 256];

// ---------------- PTX helpers (valid on compute_103) ----------------
__device__ __forceinline__ uint32_t smem_u32(const void* p) {
    uint32_t a;
    asm("{ .reg .u64 t; cvta.to.shared.u64 t, %1; cvt.u32.u64 %0, t; }" : "=r"(a) : "l"(p));
    return a;
}
__device__ __forceinline__ void ldsm4(uint32_t r[4], uint32_t addr) {
    asm volatile("ldmatrix.sync.aligned.m8n8.x4.shared.b16 {%0,%1,%2,%3}, [%4];"
                 : "=r"(r[0]), "=r"(r[1]), "=r"(r[2]), "=r"(r[3]) : "r"(addr));
}
__device__ __forceinline__ void mma16816(float c[4], const uint32_t a[4],
                                         uint32_t b0, uint32_t b1) {
    asm volatile(
        "mma.sync.aligned.m16n8k16.row.col.f32.bf16.bf16.f32 "
        "{%0,%1,%2,%3}, {%4,%5,%6,%7}, {%8,%9}, {%0,%1,%2,%3};"
        : "+f"(c[0]), "+f"(c[1]), "+f"(c[2]), "+f"(c[3])
        : "r"(a[0]), "r"(a[1]), "r"(a[2]), "r"(a[3]), "r"(b0), "r"(b1));
}
__device__ __forceinline__ void cpa16(uint32_t dst, const void* src, int sz) {
    asm volatile("cp.async.cg.shared.global [%0], [%1], 16, %2;"
                 :: "r"(dst), "l"(src), "r"(sz) : "memory");
}
#define CP_COMMIT() asm volatile("cp.async.commit_group;" ::: "memory")
#define CP_WAIT(n)  asm volatile("cp.async.wait_group %0;" :: "n"(n) : "memory")

// pack two fp32 -> one bf16x2 word (round-to-nearest)
__device__ __forceinline__ uint32_t packbf2(float f0, float f1) {
    __nv_bfloat16 h0 = __float2bfloat16(f0), h1 = __float2bfloat16(f1);
    return (uint32_t)*(uint16_t*)&h0 | ((uint32_t)*(uint16_t*)&h1 << 16);
}

// ---------------- x -> bf16 ----------------
__global__ void k_splitX(const float* __restrict__ x) {
    size_t i = (size_t)(blockIdx.x * 256 + threadIdx.x) * 4;
    float4 v = *(const float4*)(x + i);
    *(uint2*)(g_Ah + i) = make_uint2(packbf2(v.x, v.y), packbf2(v.z, v.w));
}

// ---------------- init: zero degrees + split/transpose weights ----------------
__global__ void k_init(const float* __restrict__ W1, const float* __restrict__ W2,
                       const float* __restrict__ Wo) {
    int i = blockIdx.x * 256 + threadIdx.x;
    if (i < NN) g_indeg[i] = 0;
    if (i == 0) g_total = 0;
    if (i < 65536) {
        int n = i >> 8, k = i & 255;
        float a = W1[(size_t)k * 256 + n];
        __nv_bfloat16 h = __float2bfloat16(a);
        g_W1h[i] = h;
        g_W1l[i] = __float2bfloat16(a - __bfloat162float(h));
        a = W2[(size_t)k * 256 + n];
        h = __float2bfloat16(a);
        g_W2h[i] = h;
        g_W2l[i] = __float2bfloat16(a - __bfloat162float(h));
        if (i < 16384) {
            int n2 = i >> 8, k2 = i & 255;
            a = Wo[(size_t)k2 * 64 + n2];
            h = __float2bfloat16(a);
            g_Woh[i] = h;
            g_Wol[i] = __float2bfloat16(a - __bfloat162float(h));
        }
    }
}
__global__ void k_deg(const int* __restrict__ dst) {
    int e = blockIdx.x * 256 + threadIdx.x;
    if (e < NE) atomicAdd(&g_indeg[dst[e]], 1);
}
// parallel offset assignment: warp scan + one atomic per warp (order-free CSR)
__global__ void k_off() {
    int i = blockIdx.x * 256 + threadIdx.x;
    int lane = threadIdx.x & 31;
    int d = (i < NN) ? g_indeg[i] : 0;
    int v = d;
    #pragma unroll
    for (int s = 1; s < 32; s <<= 1) {
        int t = __shfl_up_sync(0xffffffffu, v, s);
        if (lane >= s) v += t;
    }
    int wtotal = __shfl_sync(0xffffffffu, v, 31);
    int base = 0;
    if (lane == 0) base = atomicAdd(&g_total, wtotal);
    base = __shfl_sync(0xffffffffu, base, 0);
    if (i < NN) {
        int excl = base + v - d;
        g_off[i] = excl;
        g_cursor[i] = excl;
    }
}
__global__ void k_fill(const int* __restrict__ src, const int* __restrict__ dst) {
    int e = blockIdx.x * 256 + threadIdx.x;
    if (e < NE) {
        int p = atomicAdd(&g_cursor[dst[e]], 1);
        g_csrc[p] = src[e];
    }
}

// ---------------- HMMA GEMM via cp.async: C = bf16(A)[M,256] @ (Wh+Wl), 2-pass ----
// BM=128, BK=32, 256 thr (8 warps 4m x 2n), warp tile 32 x (BN/2). 2 CTAs/SM.
// MODE 0/1: C=g_bufA, row-scale by rsqrt(indeg+1)
// MODE 2:   C=Cext, + bias + fused log_softmax (BN=64)
template <int MODE, int BN>
__global__ __launch_bounds__(256, 2)
void gemm_mma(const float* __restrict__ bias, float* __restrict__ Cext)
{
    float* C = (MODE == 2) ? Cext : (float*)g_bufA;
    const __nv_bfloat16* WH = (MODE == 0) ? g_W1h : (MODE == 1) ? g_W2h : g_Woh;
    const __nv_bfloat16* WL = (MODE == 0) ? g_W1l : (MODE == 1) ? g_W2l : g_Wol;

    constexpr int WN = BN / 2;               // 64 or 32
    constexpr int NT = WN / 8;               // 8 or 4
    constexpr int A_BYTES = 128 * 80;        // 10240 (LDSE=40 elems, 80B rows)
    constexpr int B_BYTES = BN * 80;
    constexpr int STAGE = A_BYTES + 2 * B_BYTES;
    constexpr int BH = BN / 64;              // B cp.async iterations (2 or 1)
    constexpr int CS = (MODE == 2) ? 64 : 256;

    extern __shared__ char smraw[];
    uint32_t sb = smem_u32(smraw);

    int tid = threadIdx.x, lane = tid & 31, wid = tid >> 5;
    int mw = wid & 3, nw = wid >> 2;
    int bm0 = blockIdx.x * 128;
    int bn0 = blockIdx.y * BN;

    auto issue = [&](int kb, int s) {
        uint32_t base = sb + (uint32_t)s * STAGE;
        #pragma unroll
        for (int h = 0; h < 2; h++) {
            int c = tid + h * 256;
            int row = c >> 2, kq = c & 3;
            int r = bm0 + row;
            uint32_t dst = base + (uint32_t)row * 80u + (uint32_t)kq * 16u;
            size_t gp = (size_t)r * DD + kb * 32 + kq * 8;
            cpa16(dst, g_Ah + gp, (r < NN) ? 16 : 0);
        }
        #pragma unroll
        for (int h = 0; h < BH; h++) {
            int c = tid + h * 256;
            int row = c >> 2, kq = c & 3;
            uint32_t dst = base + A_BYTES + (uint32_t)row * 80u + (uint32_t)kq * 16u;
            size_t gp = (size_t)(bn0 + row) * DD + kb * 32 + kq * 8;
            cpa16(dst, WH + gp, 16);
            cpa16(dst + B_BYTES, WL + gp, 16);
        }
        CP_COMMIT();
    };

    float acc[2][NT][4];
    #pragma unroll
    for (int mt = 0; mt < 2; mt++)
        #pragma unroll
        for (int nt = 0; nt < NT; nt++)
            #pragma unroll
            for (int q = 0; q < 4; q++) acc[mt][nt][q] = 0.f;

    issue(0, 0);
    issue(1, 1);

    for (int kb = 0; kb < 8; kb++) {
        int s = kb & 1;
        if (kb < 7) { CP_WAIT(1); } else { CP_WAIT(0); }
        __syncthreads();

        // compute stage s — 2 passes: A*Wh, A*Wl
        {
            uint32_t base = sb + (uint32_t)s * STAGE;
            #pragma unroll
            for (int ks = 0; ks < 2; ks++) {
                int col = ks * 16 + (lane >> 4) * 8;
                uint32_t ah[2][4];
                uint32_t aoff = (uint32_t)((mw * 32 + (lane & 15)) * 40 + col) * 2u;
                ldsm4(ah[0], base + aoff);
                ldsm4(ah[1], base + aoff + 16 * 80);

                #pragma unroll
                for (int g = 0; g < NT / 4; g++) {
                    uint32_t bh[4][2], bl[4][2];
                    #pragma unroll
                    for (int j2 = 0; j2 < 2; j2++) {
                        int j = g * 2 + j2;
                        uint32_t boff = base + A_BYTES +
                            (uint32_t)((nw * WN + j * 16 + (lane & 15)) * 40 + col) * 2u;
                        uint32_t rh[4], rl[4];
                        ldsm4(rh, boff);
                        ldsm4(rl, boff + B_BYTES);
                        bh[2 * j2][0] = rh[0]; bh[2 * j2][1] = rh[2];
                        bh[2 * j2 + 1][0] = rh[1]; bh[2 * j2 + 1][1] = rh[3];
                        bl[2 * j2][0] = rl[0]; bl[2 * j2][1] = rl[2];
                        bl[2 * j2 + 1][0] = rl[1]; bl[2 * j2 + 1][1] = rl[3];
                    }
                    // pass 1: A*Wh  (8 independent MMAs)
                    #pragma unroll
                    for (int mt = 0; mt < 2; mt++)
                        #pragma unroll
                        for (int q = 0; q < 4; q++)
                            mma16816(acc[mt][g * 4 + q], ah[mt], bh[q][0], bh[q][1]);
                    // pass 2: A*Wl
                    #pragma unroll
                    for (int mt = 0; mt < 2; mt++)
                        #pragma unroll
                        for (int q = 0; q < 4; q++)
                            mma16816(acc[mt][g * 4 + q], ah[mt], bl[q][0], bl[q][1]);
                }
            }
        }
        if (kb < 6) {
            __syncthreads();
            issue(kb + 2, s);
        }
    }

    if (MODE != 2) {
        // ---- epilogue: inline dis = rsqrt(indeg+1), scale + store ----
        int rbase = bm0 + mw * 32 + (lane >> 2);
        int cbase = bn0 + nw * WN + (lane & 3) * 2;
        #pragma unroll
        for (int mt = 0; mt < 2; mt++) {
            int r0 = rbase + mt * 16, r1 = r0 + 8;
            float s0 = (r0 < NN) ? rsqrtf((float)(g_indeg[r0] + 1)) : 0.f;
            float s1 = (r1 < NN) ? rsqrtf((float)(g_indeg[r1] + 1)) : 0.f;
            #pragma unroll
            for (int nt = 0; nt < NT; nt++) {
                int cc = cbase + nt * 8;
                if (r0 < NN) *(float2*)(C + (size_t)r0 * CS + cc) =
                    make_float2(acc[mt][nt][0] * s0, acc[mt][nt][1] * s0);
                if (r1 < NN) *(float2*)(C + (size_t)r1 * CS + cc) =
                    make_float2(acc[mt][nt][2] * s1, acc[mt][nt][3] * s1);
            }
        }
    } else {
        // ---- epilogue: bias -> smem -> fused log_softmax -> store ----
        __syncthreads();   // all compute done before smem reuse
        float* ls = (float*)smraw;   // 128 x 64 fp32 = 32KB
        int lr0 = mw * 32 + (lane >> 2);
        int cb = nw * WN + (lane & 3) * 2;
        #pragma unroll
        for (int mt = 0; mt < 2; mt++) {
            int a0 = lr0 + mt * 16, a1 = a0 + 8;
            #pragma unroll
            for (int nt = 0; nt < NT; nt++) {
                int cc = cb + nt * 8;
                float b0 = bias[cc], b1 = bias[cc + 1];
                ls[a0 * 64 + cc] = acc[mt][nt][0] + b0;
                ls[a0 * 64 + cc + 1] = acc[mt][nt][1] + b1;
                ls[a1 * 64 + cc] = acc[mt][nt][2] + b0;
                ls[a1 * 64 + cc + 1] = acc[mt][nt][3] + b1;
            }
        }
        __syncthreads();
        #pragma unroll 1
        for (int i = 0; i < 16; i++) {
            int lr = wid * 16 + i;
            int r = bm0 + lr;
            if (r >= NN) break;
            float2 v = *(const float2*)&ls[lr * 64 + lane * 2];
            float m = fmaxf(v.x, v.y);
            #pragma unroll
            for (int d = 16; d; d >>= 1) m = fmaxf(m, __shfl_xor_sync(0xffffffffu, m, d));
            float sm = expf(v.x - m) + expf(v.y - m);
            #pragma unroll
            for (int d = 16; d; d >>= 1) sm += __shfl_xor_sync(0xffffffffu, sm, d);
            float l = m + logf(sm);
            *(float2*)(C + (size_t)r * 64 + lane * 2) = make_float2(v.x - l, v.y - l);
        }
    }
}

// ---------------- aggregation: relu(dis*(Hs[i]+sum Hs[src])+b) -> bf16 ----
__global__ __launch_bounds__(256)
void k_agg(const float* __restrict__ bias)
{
    int node = blockIdx.x * 8 + (threadIdx.x >> 5);
    int lane = threadIdx.x & 31;
    const float4* __restrict__ Hs = (const float4*)g_bufA;

    size_t base = (size_t)node * 64;
    float4 a0 = Hs[base + lane];
    float4 a1 = Hs[base + 32 + lane];

    int e = g_off[node], deg = g_indeg[node], end = e + deg;
    for (; e + 3 < end; e += 4) {
        int s0 = g_csrc[e], s1 = g_csrc[e + 1], s2 = g_csrc[e + 2], s3 = g_csrc[e + 3];
        size_t p0 = (size_t)s0 * 64, p1 = (size_t)s1 * 64;
        size_t p2 = (size_t)s2 * 64, p3 = (size_t)s3 * 64;
        float4 v0 = Hs[p0 + lane],      w0 = Hs[p1 + lane];
        float4 x0 = Hs[p2 + lane],      y0 = Hs[p3 + lane];
        float4 v1 = Hs[p0 + 32 + lane], w1 = Hs[p1 + 32 + lane];
        float4 x1 = Hs[p2 + 32 + lane], y1 = Hs[p3 + 32 + lane];
        a0.x += (v0.x + w0.x) + (x0.x + y0.x);
        a0.y += (v0.y + w0.y) + (x0.y + y0.y);
        a0.z += (v0.z + w0.z) + (x0.z + y0.z);
        a0.w += (v0.w + w0.w) + (x0.w + y0.w);
        a1.x += (v1.x + w1.x) + (x1.x + y1.x);
        a1.y += (v1.y + w1.y) + (x1.y + y1.y);
        a1.z += (v1.z + w1.z) + (x1.z + y1.z);
        a1.w += (v1.w + w1.w) + (x1.w + y1.w);
    }
    for (; e < end; e++) {
        int s0 = g_csrc[e];
        size_t p0 = (size_t)s0 * 64;
        float4 v0 = Hs[p0 + lane];
        float4 v1 = Hs[p0 + 32 + lane];
        a0.x += v0.x; a0.y += v0.y; a0.z += v0.z; a0.w += v0.w;
        a1.x += v1.x; a1.y += v1.y; a1.z += v1.z; a1.w += v1.w;
    }

    float dsc = rsqrtf((float)(deg + 1));
    float4 b0 = *(const float4*)(bias + lane * 4);
    float4 b1 = *(const float4*)(bias + 128 + lane * 4);
    float o00 = fmaxf(fmaf(dsc, a0.x, b0.x), 0.f);
    float o01 = fmaxf(fmaf(dsc, a0.y, b0.y), 0.f);
    float o02 = fmaxf(fmaf(dsc, a0.z, b0.z), 0.f);
    float o03 = fmaxf(fmaf(dsc, a0.w, b0.w), 0.f);
    float o10 = fmaxf(fmaf(dsc, a1.x, b1.x), 0.f);
    float o11 = fmaxf(fmaf(dsc, a1.y, b1.y), 0.f);
    float o12 = fmaxf(fmaf(dsc, a1.z, b1.z), 0.f);
    float o13 = fmaxf(fmaf(dsc, a1.w, b1.w), 0.f);

    size_t ob = (size_t)node * 256 + lane * 4;
    *(uint2*)(g_Ah + ob) = make_uint2(packbf2(o00, o01), packbf2(o02, o03));
    *(uint2*)(g_Ah + ob + 128) = make_uint2(packbf2(o10, o11), packbf2(o12, o13));
}

// ---------------- launch ----------------
extern "C" void kernel_launch(void* const* d_in, const int* in_sizes, int n_in,
                              void* d_out, int out_size)
{
    const float* x  = (const float*)d_in[0];
    const int*   ei = (const int*)d_in[1];
    const float* b1 = (const float*)d_in[3];
    const float* b2 = (const float*)d_in[5];
    const float* W1 = (const float*)d_in[2];
    const float* W2 = (const float*)d_in[4];
    const float* Wo = (const float*)d_in[6];
    const float* bo = (const float*)d_in[7];
    float* out = (float*)d_out;

    const int* src = ei;
    const int* dst = ei + NE;

    cudaFuncSetAttribute(gemm_mma<0, 128>, cudaFuncAttributeMaxDynamicSharedMemorySize, 61440);
    cudaFuncSetAttribute(gemm_mma<1, 128>, cudaFuncAttributeMaxDynamicSharedMemorySize, 61440);
    cudaFuncSetAttribute(gemm_mma<2, 64>,  cudaFuncAttributeMaxDynamicSharedMemorySize, 40960);

    const int GM = (NN + 127) / 128;   // 782

    k_splitX<<<NN * DD / 1024, 256>>>(x);                        // 1: x -> bf16
    k_init<<<(NN + 255) / 256, 256>>>(W1, W2, Wo);               // 2: zero deg + W split
    k_deg<<<NE / 256, 256>>>(dst);                               // 3: degrees
    gemm_mma<0, 128><<<dim3(GM, 2), 256, 61440>>>(nullptr, nullptr);  // 4: bufA = dis*(x@W1)
    k_off<<<(NN + 255) / 256, 256>>>();                          // 5: CSR offsets
    k_fill<<<NE / 256, 256>>>(src, dst);                         // 6: CSR fill
    k_agg<<<NN / 8, 256>>>(b1);                                  // 7: Ah = bf16(relu(...))
    gemm_mma<1, 128><<<dim3(GM, 2), 256, 61440>>>(nullptr, nullptr);
    k_agg<<<NN / 8, 256>>>(b2);
    gemm_mma<2, 64><<<dim3(GM, 1), 256, 40960>>>(bo, out);       // out = lsm(h@Wo + bo)
}

// round 11
// speedup vs baseline: 1.9304x; 1.5405x over previous
#include <cuda_runtime.h>
#include <cuda_bf16.h>
#include <cstdint>

#define NN 100000
#define NE 800000
#define DD 256

// ---------------- device scratch (no allocations allowed) ----------------
__device__ __align__(16) __nv_bfloat16 g_Hs[(size_t)NN * DD];   // dis-scaled h (bf16)
__device__ __align__(16) __nv_bfloat16 g_Ah[(size_t)NN * DD];   // A operand bf16 (x / relu out)
__device__ int   g_indeg[NN];
__device__ int   g_off[NN];
__device__ int   g_cursor[NN];
__device__ int   g_csrc[NE];
__device__ int   g_total;
// W bf16, pre-transposed to [N][K] (B operand, K-contiguous)
__device__ __align__(16) __nv_bfloat16 g_W1h[256 * 256];
__device__ __align__(16) __nv_bfloat16 g_W2h[256 * 256];
__device__ __align__(16) __nv_bfloat16 g_Woh[64 * 256];

// ---------------- PTX helpers (valid on compute_103) ----------------
__device__ __forceinline__ uint32_t smem_u32(const void* p) {
    uint32_t a;
    asm("{ .reg .u64 t; cvta.to.shared.u64 t, %1; cvt.u32.u64 %0, t; }" : "=r"(a) : "l"(p));
    return a;
}
__device__ __forceinline__ void ldsm4(uint32_t r[4], uint32_t addr) {
    asm volatile("ldmatrix.sync.aligned.m8n8.x4.shared.b16 {%0,%1,%2,%3}, [%4];"
                 : "=r"(r[0]), "=r"(r[1]), "=r"(r[2]), "=r"(r[3]) : "r"(addr));
}
__device__ __forceinline__ void mma16816(float c[4], const uint32_t a[4],
                                         uint32_t b0, uint32_t b1) {
    asm volatile(
        "mma.sync.aligned.m16n8k16.row.col.f32.bf16.bf16.f32 "
        "{%0,%1,%2,%3}, {%4,%5,%6,%7}, {%8,%9}, {%0,%1,%2,%3};"
        : "+f"(c[0]), "+f"(c[1]), "+f"(c[2]), "+f"(c[3])
        : "r"(a[0]), "r"(a[1]), "r"(a[2]), "r"(a[3]), "r"(b0), "r"(b1));
}
__device__ __forceinline__ void cpa16(uint32_t dst, const void* src, int sz) {
    asm volatile("cp.async.cg.shared.global [%0], [%1], 16, %2;"
                 :: "r"(dst), "l"(src), "r"(sz) : "memory");
}
#define CP_COMMIT() asm volatile("cp.async.commit_group;" ::: "memory")
#define CP_WAIT(n)  asm volatile("cp.async.wait_group %0;" :: "n"(n) : "memory")

// pack two fp32 -> one bf16x2 word (round-to-nearest)
__device__ __forceinline__ uint32_t packbf2(float f0, float f1) {
    __nv_bfloat16 h0 = __float2bfloat16(f0), h1 = __float2bfloat16(f1);
    return (uint32_t)*(uint16_t*)&h0 | ((uint32_t)*(uint16_t*)&h1 << 16);
}
// unpack bf16x2 word -> float2
__device__ __forceinline__ float2 bf2f(uint32_t w) {
    __nv_bfloat162 b;
    *reinterpret_cast<uint32_t*>(&b) = w;
    return __bfloat1622float2(b);
}
__device__ __forceinline__ void acc8(float* a, uint4 u) {
    float2 f0 = bf2f(u.x), f1 = bf2f(u.y), f2 = bf2f(u.z), f3 = bf2f(u.w);
    a[0] += f0.x; a[1] += f0.y; a[2] += f1.x; a[3] += f1.y;
    a[4] += f2.x; a[5] += f2.y; a[6] += f3.x; a[7] += f3.y;
}

// ---------------- x -> bf16 ----------------
__global__ void k_splitX(const float* __restrict__ x) {
    size_t i = (size_t)(blockIdx.x * 256 + threadIdx.x) * 4;
    float4 v = *(const float4*)(x + i);
    *(uint2*)(g_Ah + i) = make_uint2(packbf2(v.x, v.y), packbf2(v.z, v.w));
}

// ---------------- init: zero degrees + round/transpose weights ----------------
__global__ void k_init(const float* __restrict__ W1, const float* __restrict__ W2,
                       const float* __restrict__ Wo) {
    int i = blockIdx.x * 256 + threadIdx.x;
    if (i < NN) g_indeg[i] = 0;
    if (i == 0) g_total = 0;
    if (i < 65536) {
        int n = i >> 8, k = i & 255;
        g_W1h[i] = __float2bfloat16(W1[(size_t)k * 256 + n]);
        g_W2h[i] = __float2bfloat16(W2[(size_t)k * 256 + n]);
        if (i < 16384) {
            int n2 = i >> 8, k2 = i & 255;
            g_Woh[i] = __float2bfloat16(Wo[(size_t)k2 * 64 + n2]);
        }
    }
}
__global__ void k_deg(const int* __restrict__ dst) {
    int e = blockIdx.x * 256 + threadIdx.x;
    if (e < NE) atomicAdd(&g_indeg[dst[e]], 1);
}
// parallel offset assignment: warp scan + one atomic per warp (order-free CSR)
__global__ void k_off() {
    int i = blockIdx.x * 256 + threadIdx.x;
    int lane = threadIdx.x & 31;
    int d = (i < NN) ? g_indeg[i] : 0;
    int v = d;
    #pragma unroll
    for (int s = 1; s < 32; s <<= 1) {
        int t = __shfl_up_sync(0xffffffffu, v, s);
        if (lane >= s) v += t;
    }
    int wtotal = __shfl_sync(0xffffffffu, v, 31);
    int base = 0;
    if (lane == 0) base = atomicAdd(&g_total, wtotal);
    base = __shfl_sync(0xffffffffu, base, 0);
    if (i < NN) {
        int excl = base + v - d;
        g_off[i] = excl;
        g_cursor[i] = excl;
    }
}
__global__ void k_fill(const int* __restrict__ src, const int* __restrict__ dst) {
    int e = blockIdx.x * 256 + threadIdx.x;
    if (e < NE) {
        int p = atomicAdd(&g_cursor[dst[e]], 1);
        g_csrc[p] = src[e];
    }
}

// ---------------- HMMA GEMM via cp.async: single-pass bf16 -------------------
// BM=128, BK=32, 256 thr (8 warps 4m x 2n), warp tile 32 x (BN/2). 2 CTAs/SM.
// MODE 0/1: C=g_Hs (bf16), row-scale by rsqrt(indeg+1)
// MODE 2:   C=Cext (fp32), + bias + fused log_softmax (BN=64)
template <int MODE, int BN>
__global__ __launch_bounds__(256, 2)
void gemm_mma(const float* __restrict__ bias, float* __restrict__ Cext)
{
    const __nv_bfloat16* WH = (MODE == 0) ? g_W1h : (MODE == 1) ? g_W2h : g_Woh;

    constexpr int WN = BN / 2;               // 64 or 32
    constexpr int NT = WN / 8;               // 8 or 4
    constexpr int A_BYTES = 128 * 80;        // 10240 (LDSE=40 elems, 80B rows)
    constexpr int B_BYTES = BN * 80;
    constexpr int STAGE = A_BYTES + B_BYTES;
    constexpr int BH = BN / 64;              // B cp.async iterations (2 or 1)

    extern __shared__ char smraw[];
    uint32_t sb = smem_u32(smraw);

    int tid = threadIdx.x, lane = tid & 31, wid = tid >> 5;
    int mw = wid & 3, nw = wid >> 2;
    int bm0 = blockIdx.x * 128;
    int bn0 = blockIdx.y * BN;

    auto issue = [&](int kb, int s) {
        uint32_t base = sb + (uint32_t)s * STAGE;
        #pragma unroll
        for (int h = 0; h < 2; h++) {
            int c = tid + h * 256;
            int row = c >> 2, kq = c & 3;
            int r = bm0 + row;
            uint32_t dst = base + (uint32_t)row * 80u + (uint32_t)kq * 16u;
            size_t gp = (size_t)r * DD + kb * 32 + kq * 8;
            cpa16(dst, g_Ah + gp, (r < NN) ? 16 : 0);
        }
        #pragma unroll
        for (int h = 0; h < BH; h++) {
            int c = tid + h * 256;
            int row = c >> 2, kq = c & 3;
            uint32_t dst = base + A_BYTES + (uint32_t)row * 80u + (uint32_t)kq * 16u;
            size_t gp = (size_t)(bn0 + row) * DD + kb * 32 + kq * 8;
            cpa16(dst, WH + gp, 16);
        }
        CP_COMMIT();
    };

    float acc[2][NT][4];
    #pragma unroll
    for (int mt = 0; mt < 2; mt++)
        #pragma unroll
        for (int nt = 0; nt < NT; nt++)
            #pragma unroll
            for (int q = 0; q < 4; q++) acc[mt][nt][q] = 0.f;

    issue(0, 0);
    issue(1, 1);

    for (int kb = 0; kb < 8; kb++) {
        int s = kb & 1;
        if (kb < 7) { CP_WAIT(1); } else { CP_WAIT(0); }
        __syncthreads();

        // compute stage s — single bf16 pass
        {
            uint32_t base = sb + (uint32_t)s * STAGE;
            #pragma unroll
            for (int ks = 0; ks < 2; ks++) {
                int col = ks * 16 + (lane >> 4) * 8;
                uint32_t ah[2][4];
                uint32_t aoff = (uint32_t)((mw * 32 + (lane & 15)) * 40 + col) * 2u;
                ldsm4(ah[0], base + aoff);
                ldsm4(ah[1], base + aoff + 16 * 80);

                #pragma unroll
                for (int g = 0; g < NT / 4; g++) {
                    uint32_t bh[4][2];
                    #pragma unroll
                    for (int j2 = 0; j2 < 2; j2++) {
                        int j = g * 2 + j2;
                        uint32_t boff = base + A_BYTES +
                            (uint32_t)((nw * WN + j * 16 + (lane & 15)) * 40 + col) * 2u;
                        uint32_t rh[4];
                        ldsm4(rh, boff);
                        bh[2 * j2][0] = rh[0]; bh[2 * j2][1] = rh[2];
                        bh[2 * j2 + 1][0] = rh[1]; bh[2 * j2 + 1][1] = rh[3];
                    }
                    #pragma unroll
                    for (int mt = 0; mt < 2; mt++)
                        #pragma unroll
                        for (int q = 0; q < 4; q++)
                            mma16816(acc[mt][g * 4 + q], ah[mt], bh[q][0], bh[q][1]);
                }
            }
        }
        if (kb < 6) {
            __syncthreads();
            issue(kb + 2, s);
        }
    }

    if (MODE != 2) {
        // ---- epilogue: dis = rsqrt(indeg+1), scale + bf16 store to g_Hs ----
        int rbase = bm0 + mw * 32 + (lane >> 2);
        int cbase = bn0 + nw * WN + (lane & 3) * 2;
        #pragma unroll
        for (int mt = 0; mt < 2; mt++) {
            int r0 = rbase + mt * 16, r1 = r0 + 8;
            float s0 = (r0 < NN) ? rsqrtf((float)(g_indeg[r0] + 1)) : 0.f;
            float s1 = (r1 < NN) ? rsqrtf((float)(g_indeg[r1] + 1)) : 0.f;
            #pragma unroll
            for (int nt = 0; nt < NT; nt++) {
                int cc = cbase + nt * 8;
                if (r0 < NN) *(uint32_t*)(g_Hs + (size_t)r0 * 256 + cc) =
                    packbf2(acc[mt][nt][0] * s0, acc[mt][nt][1] * s0);
                if (r1 < NN) *(uint32_t*)(g_Hs + (size_t)r1 * 256 + cc) =
                    packbf2(acc[mt][nt][2] * s1, acc[mt][nt][3] * s1);
            }
        }
    } else {
        // ---- epilogue: bias -> smem -> fused log_softmax -> fp32 store ----
        __syncthreads();   // all compute done before smem reuse
        float* ls = (float*)smraw;   // 128 x 64 fp32 = 32KB
        int lr0 = mw * 32 + (lane >> 2);
        int cb = nw * WN + (lane & 3) * 2;
        #pragma unroll
        for (int mt = 0; mt < 2; mt++) {
            int a0 = lr0 + mt * 16, a1 = a0 + 8;
            #pragma unroll
            for (int nt = 0; nt < NT; nt++) {
                int cc = cb + nt * 8;
                float b0 = bias[cc], b1 = bias[cc + 1];
                ls[a0 * 64 + cc] = acc[mt][nt][0] + b0;
                ls[a0 * 64 + cc + 1] = acc[mt][nt][1] + b1;
                ls[a1 * 64 + cc] = acc[mt][nt][2] + b0;
                ls[a1 * 64 + cc + 1] = acc[mt][nt][3] + b1;
            }
        }
        __syncthreads();
        #pragma unroll 1
        for (int i = 0; i < 16; i++) {
            int lr = wid * 16 + i;
            int r = bm0 + lr;
            if (r >= NN) break;
            float2 v = *(const float2*)&ls[lr * 64 + lane * 2];
            float m = fmaxf(v.x, v.y);
            #pragma unroll
            for (int d = 16; d; d >>= 1) m = fmaxf(m, __shfl_xor_sync(0xffffffffu, m, d));
            float sm = expf(v.x - m) + expf(v.y - m);
            #pragma unroll
            for (int d = 16; d; d >>= 1) sm += __shfl_xor_sync(0xffffffffu, sm, d);
            float l = m + logf(sm);
            *(float2*)(Cext + (size_t)r * 64 + lane * 2) = make_float2(v.x - l, v.y - l);
        }
    }
}

// ---------------- aggregation (bf16 gather): relu(dis*(Hs[i]+sum Hs[src])+b) -> bf16 ----
__global__ __launch_bounds__(256)
void k_agg(const float* __restrict__ bias)
{
    int node = blockIdx.x * 8 + (threadIdx.x >> 5);
    int lane = threadIdx.x & 31;
    const __nv_bfloat16* __restrict__ Hs = g_Hs;

    size_t self = (size_t)node * 256 + lane * 8;
    float a[8];
    {
        uint4 u = *(const uint4*)(Hs + self);
        float2 f0 = bf2f(u.x), f1 = bf2f(u.y), f2 = bf2f(u.z), f3 = bf2f(u.w);
        a[0] = f0.x; a[1] = f0.y; a[2] = f1.x; a[3] = f1.y;
        a[4] = f2.x; a[5] = f2.y; a[6] = f3.x; a[7] = f3.y;
    }

    int e = g_off[node], deg = g_indeg[node], end = e + deg;
    for (; e + 3 < end; e += 4) {
        int s0 = g_csrc[e], s1 = g_csrc[e + 1], s2 = g_csrc[e + 2], s3 = g_csrc[e + 3];
        uint4 u0 = *(const uint4*)(Hs + (size_t)s0 * 256 + lane * 8);
        uint4 u1 = *(const uint4*)(Hs + (size_t)s1 * 256 + lane * 8);
        uint4 u2 = *(const uint4*)(Hs + (size_t)s2 * 256 + lane * 8);
        uint4 u3 = *(const uint4*)(Hs + (size_t)s3 * 256 + lane * 8);
        acc8(a, u0); acc8(a, u1); acc8(a, u2); acc8(a, u3);
    }
    for (; e < end; e++) {
        int s0 = g_csrc[e];
        uint4 u0 = *(const uint4*)(Hs + (size_t)s0 * 256 + lane * 8);
        acc8(a, u0);
    }

    float dsc = rsqrtf((float)(deg + 1));
    float4 b0 = *(const float4*)(bias + lane * 8);
    float4 b1 = *(const float4*)(bias + lane * 8 + 4);
    float o0 = fmaxf(fmaf(dsc, a[0], b0.x), 0.f);
    float o1 = fmaxf(fmaf(dsc, a[1], b0.y), 0.f);
    float o2 = fmaxf(fmaf(dsc, a[2], b0.z), 0.f);
    float o3 = fmaxf(fmaf(dsc, a[3], b0.w), 0.f);
    float o4 = fmaxf(fmaf(dsc, a[4], b1.x), 0.f);
    float o5 = fmaxf(fmaf(dsc, a[5], b1.y), 0.f);
    float o6 = fmaxf(fmaf(dsc, a[6], b1.z), 0.f);
    float o7 = fmaxf(fmaf(dsc, a[7], b1.w), 0.f);

    uint4 w;
    w.x = packbf2(o0, o1); w.y = packbf2(o2, o3);
    w.z = packbf2(o4, o5); w.w = packbf2(o6, o7);
    *(uint4*)(g_Ah + self) = w;
}

// ---------------- launch ----------------
extern "C" void kernel_launch(void* const* d_in, const int* in_sizes, int n_in,
                              void* d_out, int out_size)
{
    const float* x  = (const float*)d_in[0];
    const int*   ei = (const int*)d_in[1];
    const float* b1 = (const float*)d_in[3];
    const float* b2 = (const float*)d_in[5];
    const float* W1 = (const float*)d_in[2];
    const float* W2 = (const float*)d_in[4];
    const float* Wo = (const float*)d_in[6];
    const float* bo = (const float*)d_in[7];
    float* out = (float*)d_out;

    const int* src = ei;
    const int* dst = ei + NE;

    cudaFuncSetAttribute(gemm_mma<0, 128>, cudaFuncAttributeMaxDynamicSharedMemorySize, 40960);
    cudaFuncSetAttribute(gemm_mma<1, 128>, cudaFuncAttributeMaxDynamicSharedMemorySize, 40960);
    cudaFuncSetAttribute(gemm_mma<2, 64>,  cudaFuncAttributeMaxDynamicSharedMemorySize, 32768);

    const int GM = (NN + 127) / 128;   // 782

    k_splitX<<<NN * DD / 1024, 256>>>(x);                        // 1: x -> bf16
    k_init<<<(NN + 255) / 256, 256>>>(W1, W2, Wo);               // 2: zero deg + W bf16
    k_deg<<<NE / 256, 256>>>(dst);                               // 3: degrees
    gemm_mma<0, 128><<<dim3(GM, 2), 256, 40960>>>(nullptr, nullptr);  // 4: Hs = dis*(x@W1)
    k_off<<<(NN + 255) / 256, 256>>>();                          // 5: CSR offsets
    k_fill<<<NE / 256, 256>>>(src, dst);                         // 6: CSR fill
    k_agg<<<NN / 8, 256>>>(b1);                                  // 7: Ah = bf16(relu(...))
    gemm_mma<1, 128><<<dim3(GM, 2), 256, 40960>>>(nullptr, nullptr);
    k_agg<<<NN / 8, 256>>>(b2);
    gemm_mma<2, 64><<<dim3(GM, 1), 256, 32768>>>(bo, out);       // out = lsm(h@Wo + bo)
}

// round 12
// speedup vs baseline: 2.0165x; 1.0446x over previous
#include <cuda_runtime.h>
#include <cuda_bf16.h>
#include <cstdint>

#define NN 100000
#define NE 800000
#define DD 256

// ---------------- device scratch (no allocations allowed) ----------------
__device__ __align__(16) __nv_bfloat16 g_Hs[(size_t)NN * DD];   // dis-scaled h (bf16)
__device__ __align__(16) __nv_bfloat16 g_Ah[(size_t)NN * DD];   // A operand bf16 (x / relu out)
__device__ int   g_indeg[NN];
__device__ int   g_off[NN];
__device__ int   g_epos[NE];
__device__ int   g_csrc[NE];
__device__ int   g_total;
// W bf16, pre-transposed to [N][K] (B operand, K-contiguous)
__device__ __align__(16) __nv_bfloat16 g_W1h[256 * 256];
__device__ __align__(16) __nv_bfloat16 g_W2h[256 * 256];
__device__ __align__(16) __nv_bfloat16 g_Woh[64 * 256];

// ---------------- PTX helpers (valid on compute_103) ----------------
__device__ __forceinline__ uint32_t smem_u32(const void* p) {
    uint32_t a;
    asm("{ .reg .u64 t; cvta.to.shared.u64 t, %1; cvt.u32.u64 %0, t; }" : "=r"(a) : "l"(p));
    return a;
}
__device__ __forceinline__ void ldsm4(uint32_t r[4], uint32_t addr) {
    asm volatile("ldmatrix.sync.aligned.m8n8.x4.shared.b16 {%0,%1,%2,%3}, [%4];"
                 : "=r"(r[0]), "=r"(r[1]), "=r"(r[2]), "=r"(r[3]) : "r"(addr));
}
__device__ __forceinline__ void mma16816(float c[4], const uint32_t a[4],
                                         uint32_t b0, uint32_t b1) {
    asm volatile(
        "mma.sync.aligned.m16n8k16.row.col.f32.bf16.bf16.f32 "
        "{%0,%1,%2,%3}, {%4,%5,%6,%7}, {%8,%9}, {%0,%1,%2,%3};"
        : "+f"(c[0]), "+f"(c[1]), "+f"(c[2]), "+f"(c[3])
        : "r"(a[0]), "r"(a[1]), "r"(a[2]), "r"(a[3]), "r"(b0), "r"(b1));
}
__device__ __forceinline__ void cpa16(uint32_t dst, const void* src, int sz) {
    asm volatile("cp.async.cg.shared.global [%0], [%1], 16, %2;"
                 :: "r"(dst), "l"(src), "r"(sz) : "memory");
}
#define CP_COMMIT() asm volatile("cp.async.commit_group;" ::: "memory")
#define CP_WAIT(n)  asm volatile("cp.async.wait_group %0;" :: "n"(n) : "memory")

// pack two fp32 -> one bf16x2 word (round-to-nearest)
__device__ __forceinline__ uint32_t packbf2(float f0, float f1) {
    __nv_bfloat16 h0 = __float2bfloat16(f0), h1 = __float2bfloat16(f1);
    return (uint32_t)*(uint16_t*)&h0 | ((uint32_t)*(uint16_t*)&h1 << 16);
}
// unpack bf16x2 word -> float2
__device__ __forceinline__ float2 bf2f(uint32_t w) {
    __nv_bfloat162 b;
    *reinterpret_cast<uint32_t*>(&b) = w;
    return __bfloat1622float2(b);
}
__device__ __forceinline__ void acc8(float* a, uint4 u) {
    float2 f0 = bf2f(u.x), f1 = bf2f(u.y), f2 = bf2f(u.z), f3 = bf2f(u.w);
    a[0] += f0.x; a[1] += f0.y; a[2] += f1.x; a[3] += f1.y;
    a[4] += f2.x; a[5] += f2.y; a[6] += f3.x; a[7] += f3.y;
}

// ---------------- prep: x->bf16, W->bf16 transposed, zero deg ----------------
__global__ void k_prep(const float* __restrict__ x, const float* __restrict__ W1,
                       const float* __restrict__ W2, const float* __restrict__ Wo) {
    int gid = blockIdx.x * 256 + threadIdx.x;
    size_t i = (size_t)gid * 4;
    float4 v = *(const float4*)(x + i);
    *(uint2*)(g_Ah + i) = make_uint2(packbf2(v.x, v.y), packbf2(v.z, v.w));

    if (gid < NN) g_indeg[gid] = 0;
    if (gid == 0) g_total = 0;
    if (gid < 65536) {
        int n = gid >> 8, k = gid & 255;
        g_W1h[gid] = __float2bfloat16(W1[(size_t)k * 256 + n]);
        g_W2h[gid] = __float2bfloat16(W2[(size_t)k * 256 + n]);
        if (gid < 16384) {
            int n2 = gid >> 8, k2 = gid & 255;
            g_Woh[gid] = __float2bfloat16(Wo[(size_t)k2 * 64 + n2]);
        }
    }
}
// degree count + per-edge slot reservation
__global__ void k_deg(const int* __restrict__ dst) {
    int e = blockIdx.x * 256 + threadIdx.x;
    if (e < NE) g_epos[e] = atomicAdd(&g_indeg[dst[e]], 1);
}
// parallel offset assignment: warp scan + one atomic per warp (order-free CSR)
__global__ void k_off() {
    int i = blockIdx.x * 256 + threadIdx.x;
    int lane = threadIdx.x & 31;
    int d = (i < NN) ? g_indeg[i] : 0;
    int v = d;
    #pragma unroll
    for (int s = 1; s < 32; s <<= 1) {
        int t = __shfl_up_sync(0xffffffffu, v, s);
        if (lane >= s) v += t;
    }
    int wtotal = __shfl_sync(0xffffffffu, v, 31);
    int base = 0;
    if (lane == 0) base = atomicAdd(&g_total, wtotal);
    base = __shfl_sync(0xffffffffu, base, 0);
    if (i < NN) g_off[i] = base + v - d;
}
// atomic-free scatter using reserved slots
__global__ void k_scatter(const int* __restrict__ src, const int* __restrict__ dst) {
    int e = blockIdx.x * 256 + threadIdx.x;
    if (e < NE) g_csrc[g_off[dst[e]] + g_epos[e]] = src[e];
}

// ---------------- HMMA GEMM, 4-stage cp.async ring, single bf16 pass ---------
// BM=128, BK=32, 256 thr (8 warps 4m x 2n), warp tile 32 x (BN/2). 2 CTAs/SM.
// MODE 0/1: C=g_Hs (bf16), row-scale by rsqrt(indeg+1)
// MODE 2:   C=Cext (fp32), + bias + fused log_softmax (BN=64)
template <int MODE, int BN>
__global__ __launch_bounds__(256, 2)
void gemm_mma(const float* __restrict__ bias, float* __restrict__ Cext)
{
    const __nv_bfloat16* WH = (MODE == 0) ? g_W1h : (MODE == 1) ? g_W2h : g_Woh;

    constexpr int WN = BN / 2;               // 64 or 32
    constexpr int NT = WN / 8;               // 8 or 4
    constexpr int A_BYTES = 128 * 80;        // 10240 (LDSE=40 elems, 80B rows)
    constexpr int B_BYTES = BN * 80;
    constexpr int STAGE = A_BYTES + B_BYTES;
    constexpr int BH = BN / 64;              // B cp.async iterations (2 or 1)

    extern __shared__ char smraw[];
    uint32_t sb = smem_u32(smraw);

    int tid = threadIdx.x, lane = tid & 31, wid = tid >> 5;
    int mw = wid & 3, nw = wid >> 2;
    int bm0 = blockIdx.x * 128;
    int bn0 = blockIdx.y * BN;

    auto issue = [&](int kb) {
        uint32_t base = sb + (uint32_t)(kb & 3) * STAGE;
        #pragma unroll
        for (int h = 0; h < 2; h++) {
            int c = tid + h * 256;
            int row = c >> 2, kq = c & 3;
            int r = bm0 + row;
            uint32_t dst = base + (uint32_t)row * 80u + (uint32_t)kq * 16u;
            size_t gp = (size_t)r * DD + kb * 32 + kq * 8;
            cpa16(dst, g_Ah + gp, (r < NN) ? 16 : 0);
        }
        #pragma unroll
        for (int h = 0; h < BH; h++) {
            int c = tid + h * 256;
            int row = c >> 2, kq = c & 3;
            uint32_t dst = base + A_BYTES + (uint32_t)row * 80u + (uint32_t)kq * 16u;
            size_t gp = (size_t)(bn0 + row) * DD + kb * 32 + kq * 8;
            cpa16(dst, WH + gp, 16);
        }
        CP_COMMIT();
    };

    float acc[2][NT][4];
    #pragma unroll
    for (int mt = 0; mt < 2; mt++)
        #pragma unroll
        for (int nt = 0; nt < NT; nt++)
            #pragma unroll
            for (int q = 0; q < 4; q++) acc[mt][nt][q] = 0.f;

    issue(0); issue(1); issue(2);

    for (int kb = 0; kb < 8; kb++) {
        CP_WAIT(2);            // chunk kb complete (tail kept aligned w/ empty groups)
        __syncthreads();       // all warps done with stage (kb-1)&3 == (kb+3)&3
        if (kb + 3 < 8) issue(kb + 3); else CP_COMMIT();

        uint32_t base = sb + (uint32_t)(kb & 3) * STAGE;
        #pragma unroll
        for (int ks = 0; ks < 2; ks++) {
            int col = ks * 16 + (lane >> 4) * 8;
            uint32_t ah[2][4];
            uint32_t aoff = (uint32_t)((mw * 32 + (lane & 15)) * 40 + col) * 2u;
            ldsm4(ah[0], base + aoff);
            ldsm4(ah[1], base + aoff + 16 * 80);

            #pragma unroll
            for (int g = 0; g < NT / 4; g++) {
                uint32_t bh[4][2];
                #pragma unroll
                for (int j2 = 0; j2 < 2; j2++) {
                    int j = g * 2 + j2;
                    uint32_t boff = base + A_BYTES +
                        (uint32_t)((nw * WN + j * 16 + (lane & 15)) * 40 + col) * 2u;
                    uint32_t rh[4];
                    ldsm4(rh, boff);
                    bh[2 * j2][0] = rh[0]; bh[2 * j2][1] = rh[2];
                    bh[2 * j2 + 1][0] = rh[1]; bh[2 * j2 + 1][1] = rh[3];
                }
                #pragma unroll
                for (int mt = 0; mt < 2; mt++)
                    #pragma unroll
                    for (int q = 0; q < 4; q++)
                        mma16816(acc[mt][g * 4 + q], ah[mt], bh[q][0], bh[q][1]);
            }
        }
    }

    if (MODE != 2) {
        // ---- epilogue: dis = rsqrt(indeg+1), scale + bf16 store to g_Hs ----
        int rbase = bm0 + mw * 32 + (lane >> 2);
        int cbase = bn0 + nw * WN + (lane & 3) * 2;
        #pragma unroll
        for (int mt = 0; mt < 2; mt++) {
            int r0 = rbase + mt * 16, r1 = r0 + 8;
            float s0 = (r0 < NN) ? rsqrtf((float)(g_indeg[r0] + 1)) : 0.f;
            float s1 = (r1 < NN) ? rsqrtf((float)(g_indeg[r1] + 1)) : 0.f;
            #pragma unroll
            for (int nt = 0; nt < NT; nt++) {
                int cc = cbase + nt * 8;
                if (r0 < NN) *(uint32_t*)(g_Hs + (size_t)r0 * 256 + cc) =
                    packbf2(acc[mt][nt][0] * s0, acc[mt][nt][1] * s0);
                if (r1 < NN) *(uint32_t*)(g_Hs + (size_t)r1 * 256 + cc) =
                    packbf2(acc[mt][nt][2] * s1, acc[mt][nt][3] * s1);
            }
        }
    } else {
        // ---- epilogue: bias -> smem -> fused log_softmax -> fp32 store ----
        __syncthreads();   // all compute done before smem reuse
        float* ls = (float*)smraw;   // 128 x 64 fp32 = 32KB
        int lr0 = mw * 32 + (lane >> 2);
        int cb = nw * WN + (lane & 3) * 2;
        #pragma unroll
        for (int mt = 0; mt < 2; mt++) {
            int a0 = lr0 + mt * 16, a1 = a0 + 8;
            #pragma unroll
            for (int nt = 0; nt < NT; nt++) {
                int cc = cb + nt * 8;
                float b0 = bias[cc], b1 = bias[cc + 1];
                ls[a0 * 64 + cc] = acc[mt][nt][0] + b0;
                ls[a0 * 64 + cc + 1] = acc[mt][nt][1] + b1;
                ls[a1 * 64 + cc] = acc[mt][nt][2] + b0;
                ls[a1 * 64 + cc + 1] = acc[mt][nt][3] + b1;
            }
        }
        __syncthreads();
        #pragma unroll 1
        for (int i = 0; i < 16; i++) {
            int lr = wid * 16 + i;
            int r = bm0 + lr;
            if (r >= NN) break;
            float2 v = *(const float2*)&ls[lr * 64 + lane * 2];
            float m = fmaxf(v.x, v.y);
            #pragma unroll
            for (int d = 16; d; d >>= 1) m = fmaxf(m, __shfl_xor_sync(0xffffffffu, m, d));
            float sm = expf(v.x - m) + expf(v.y - m);
            #pragma unroll
            for (int d = 16; d; d >>= 1) sm += __shfl_xor_sync(0xffffffffu, sm, d);
            float l = m + logf(sm);
            *(float2*)(Cext + (size_t)r * 64 + lane * 2) = make_float2(v.x - l, v.y - l);
        }
    }
}

// ---------------- aggregation (bf16 gather): relu(dis*(Hs[i]+sum Hs[src])+b) -> bf16 ----
__global__ __launch_bounds__(256)
void k_agg(const float* __restrict__ bias)
{
    int node = blockIdx.x * 8 + (threadIdx.x >> 5);
    int lane = threadIdx.x & 31;
    const __nv_bfloat16* __restrict__ Hs = g_Hs;

    size_t self = (size_t)node * 256 + lane * 8;
    float a[8];
    {
        uint4 u = *(const uint4*)(Hs + self);
        float2 f0 = bf2f(u.x), f1 = bf2f(u.y), f2 = bf2f(u.z), f3 = bf2f(u.w);
        a[0] = f0.x; a[1] = f0.y; a[2] = f1.x; a[3] = f1.y;
        a[4] = f2.x; a[5] = f2.y; a[6] = f3.x; a[7] = f3.y;
    }

    int e = g_off[node], deg = g_indeg[node], end = e + deg;
    for (; e + 3 < end; e += 4) {
        int s0 = g_csrc[e], s1 = g_csrc[e + 1], s2 = g_csrc[e + 2], s3 = g_csrc[e + 3];
        uint4 u0 = *(const uint4*)(Hs + (size_t)s0 * 256 + lane * 8);
        uint4 u1 = *(const uint4*)(Hs + (size_t)s1 * 256 + lane * 8);
        uint4 u2 = *(const uint4*)(Hs + (size_t)s2 * 256 + lane * 8);
        uint4 u3 = *(const uint4*)(Hs + (size_t)s3 * 256 + lane * 8);
        acc8(a, u0); acc8(a, u1); acc8(a, u2); acc8(a, u3);
    }
    for (; e < end; e++) {
        int s0 = g_csrc[e];
        uint4 u0 = *(const uint4*)(Hs + (size_t)s0 * 256 + lane * 8);
        acc8(a, u0);
    }

    float dsc = rsqrtf((float)(deg + 1));
    float4 b0 = *(const float4*)(bias + lane * 8);
    float4 b1 = *(const float4*)(bias + lane * 8 + 4);
    float o0 = fmaxf(fmaf(dsc, a[0], b0.x), 0.f);
    float o1 = fmaxf(fmaf(dsc, a[1], b0.y), 0.f);
    float o2 = fmaxf(fmaf(dsc, a[2], b0.z), 0.f);
    float o3 = fmaxf(fmaf(dsc, a[3], b0.w), 0.f);
    float o4 = fmaxf(fmaf(dsc, a[4], b1.x), 0.f);
    float o5 = fmaxf(fmaf(dsc, a[5], b1.y), 0.f);
    float o6 = fmaxf(fmaf(dsc, a[6], b1.z), 0.f);
    float o7 = fmaxf(fmaf(dsc, a[7], b1.w), 0.f);

    uint4 w;
    w.x = packbf2(o0, o1); w.y = packbf2(o2, o3);
    w.z = packbf2(o4, o5); w.w = packbf2(o6, o7);
    *(uint4*)(g_Ah + self) = w;
}

// ---------------- launch ----------------
extern "C" void kernel_launch(void* const* d_in, const int* in_sizes, int n_in,
                              void* d_out, int out_size)
{
    const float* x  = (const float*)d_in[0];
    const int*   ei = (const int*)d_in[1];
    const float* b1 = (const float*)d_in[3];
    const float* b2 = (const float*)d_in[5];
    const float* W1 = (const float*)d_in[2];
    const float* W2 = (const float*)d_in[4];
    const float* Wo = (const float*)d_in[6];
    const float* bo = (const float*)d_in[7];
    float* out = (float*)d_out;

    const int* src = ei;
    const int* dst = ei + NE;

    cudaFuncSetAttribute(gemm_mma<0, 128>, cudaFuncAttributeMaxDynamicSharedMemorySize, 81920);
    cudaFuncSetAttribute(gemm_mma<1, 128>, cudaFuncAttributeMaxDynamicSharedMemorySize, 81920);
    cudaFuncSetAttribute(gemm_mma<2, 64>,  cudaFuncAttributeMaxDynamicSharedMemorySize, 61440);

    const int GM = (NN + 127) / 128;   // 782

    k_prep<<<NN * DD / 1024, 256>>>(x, W1, W2, Wo);              // 1: x/W -> bf16, zero deg
    k_deg<<<NE / 256, 256>>>(dst);                               // 2: degrees + edge slots
    k_off<<<(NN + 255) / 256, 256>>>();                          // 3: CSR offsets
    gemm_mma<0, 128><<<dim3(GM, 2), 256, 81920>>>(nullptr, nullptr);  // 4: Hs = dis*(x@W1)
    k_scatter<<<NE / 256, 256>>>(src, dst);                      // 5: CSR fill (no atomics)
    k_agg<<<NN / 8, 256>>>(b1);                                  // 6: Ah = bf16(relu(...))
    gemm_mma<1, 128><<<dim3(GM, 2), 256, 81920>>>(nullptr, nullptr);
    k_agg<<<NN / 8, 256>>>(b2);
    gemm_mma<2, 64><<<dim3(GM, 1), 256, 61440>>>(bo, out);       // out = lsm(h@Wo + bo)
}